// round 13
// baseline (speedup 1.0000x reference)
#include <cuda_runtime.h>
#include <cuda_bf16.h>
#include <cuda_fp16.h>
#include <cstdint>

#define BB 2
#define TT 1024
#define DD 1024
#define VV 32000
#define LL 8
#define MD (TT * DD)
#define AA (TT * TT)

typedef __nv_bfloat16 bf16;

__device__ float g_x[BB * MD];
__device__ float g_a[BB * AA];
__device__ float g_o[BB * MD];
__device__ bf16 g_xh[BB * MD], g_xl[BB * MD];
__device__ bf16 g_qh[BB * MD], g_ql[BB * MD];
__device__ bf16 g_kh[BB * MD], g_kl[BB * MD];
__device__ bf16 g_qwh[LL * DD * DD], g_qwl[LL * DD * DD];
__device__ bf16 g_kwh[LL * DD * DD], g_kwl[LL * DD * DD];
__device__ __half g_xf[BB * MD];
__device__ __half g_vf[BB * MD];          // V^T [b][d][t]
__device__ __half g_wf[BB * AA];
__device__ __half g_vwf[LL * DD * DD];
__device__ __half g_dwf[VV * DD];
__device__ __half g_xnf[BB * MD];

// 64B rows + XOR swizzle: chunk c (16B) of row r at r*64 + (c ^ ((r>>1)&3))*16.
#define SWZ(r, c) ((((uint32_t)(r)) << 6) + ((((c) ^ (((r) >> 1) & 3))) << 4))

__device__ __forceinline__ uint32_t smem_u32(const void* p) {
    uint32_t a;
    asm("{ .reg .u64 t; cvta.to.shared.u64 t, %1; cvt.u32.u64 %0, t; }" : "=r"(a) : "l"(p));
    return a;
}
#define LDM4(r0, r1, r2, r3, ad) \
    asm volatile("ldmatrix.sync.aligned.m8n8.x4.shared.b16 {%0,%1,%2,%3},[%4];" \
                 : "=r"(r0), "=r"(r1), "=r"(r2), "=r"(r3) : "r"(ad))
#define MMA16B(c, a, b0_, b1_) \
    asm volatile("mma.sync.aligned.m16n8k16.row.col.f32.bf16.bf16.f32 " \
                 "{%0,%1,%2,%3},{%4,%5,%6,%7},{%8,%9},{%0,%1,%2,%3};" \
                 : "+f"((c)[0]), "+f"((c)[1]), "+f"((c)[2]), "+f"((c)[3]) \
                 : "r"((a)[0]), "r"((a)[1]), "r"((a)[2]), "r"((a)[3]), "r"(b0_), "r"(b1_))
#define MMA16H(c, a, b0_, b1_) \
    asm volatile("mma.sync.aligned.m16n8k16.row.col.f32.f16.f16.f32 " \
                 "{%0,%1,%2,%3},{%4,%5,%6,%7},{%8,%9},{%0,%1,%2,%3};" \
                 : "+f"((c)[0]), "+f"((c)[1]), "+f"((c)[2]), "+f"((c)[3]) \
                 : "r"((a)[0]), "r"((a)[1]), "r"((a)[2]), "r"((a)[3]), "r"(b0_), "r"(b1_))
#define CPA16(d, s) asm volatile("cp.async.cg.shared.global [%0], [%1], 16;" :: "r"(d), "l"(s))
#define CPCOMMIT()  asm volatile("cp.async.commit_group;" ::: "memory")
#define CPWAIT1()   asm volatile("cp.async.wait_group 1;" ::: "memory")
#define CPWAIT0()   asm volatile("cp.async.wait_group 0;" ::: "memory")

__device__ __forceinline__ void bsplit(float v, bf16& h, bf16& l) {
    h = __float2bfloat16_rn(v);
    l = __float2bfloat16_rn(v - __bfloat162float(h));
}

// ---------------------------------------------------------------------------
// bf16 3-term split core: MT=64, 256 thr (2x4 warps of 32x32), N tile 128,
// BK=64, double buffer, 2 CTAs/SM target. smem = 98304 B.
// ---------------------------------------------------------------------------
template <int BIAS, int OUT>
__device__ __forceinline__ void gemm_core(
    const bf16* __restrict__ Ah, const bf16* __restrict__ Al, int lda,
    const bf16* __restrict__ Bh, const bf16* __restrict__ Bl, int ldb,
    const float* __restrict__ bias,
    float* __restrict__ Cf, bf16* __restrict__ Ch, bf16* __restrict__ Cl, int ldc,
    int m0, int n0, int Keff)
{
    constexpr int ABY = 64 * 64;               // 4096
    constexpr int BBY = 8192;                  // 128 rows x 64 B
    constexpr int STG32 = 2 * ABY + 2 * BBY;   // 24576
    constexpr int STG64 = 2 * STG32;           // 49152
    extern __shared__ uint16_t sm[];
    const uint32_t sb = smem_u32(sm);
    const int tid = threadIdx.x, lane = tid & 31, wrp = tid >> 5;
    const int wm = wrp >> 2, wn = wrp & 3;
    const int S2 = Keff >> 6;

    const int a_ml = (lane & 7) + ((lane >> 3) & 1) * 8;
    const int a_c0 = lane >> 4;
    const int b_nl = (lane & 7) + ((lane >> 4) << 3);
    const int b_c0 = (lane >> 3) & 1;

    const int row = tid >> 2, ch = tid & 3;
    const bf16* Aph = Ah + (long)(m0 + row) * lda + ch * 8;
    const bf16* Apl = Al + (long)(m0 + row) * lda + ch * 8;
    const bf16* Bph = Bh + (long)(n0 + row) * ldb + ch * 8;
    const bf16* Bpl = Bl + (long)(n0 + row) * ldb + ch * 8;
    const uint32_t swz = SWZ(row, ch);
    const uint32_t swz2 = SWZ(row + 64, ch);

    auto issue32 = [&](int k32, uint32_t db) {
        const int k0 = k32 << 5;
        CPA16(db + swz,                  Aph + k0);
        CPA16(db + ABY + swz,            Apl + k0);
        CPA16(db + 2 * ABY + swz,        Bph + k0);
        CPA16(db + 2 * ABY + swz2,       Bph + (long)64 * ldb + k0);
        CPA16(db + 2 * ABY + BBY + swz,  Bpl + k0);
        CPA16(db + 2 * ABY + BBY + swz2, Bpl + (long)64 * ldb + k0);
    };
    auto issue = [&](int s2) {
        const uint32_t db = sb + (uint32_t)(s2 & 1) * STG64;
        issue32(2 * s2, db);
        issue32(2 * s2 + 1, db + STG32);
        CPCOMMIT();
    };

    float acc[2][4][4] = {};

    auto compute32 = [&](uint32_t stb) {
        const uint32_t ahb = stb, alb = stb + ABY, bhb = stb + 2 * ABY, blb = bhb + BBY;
#pragma unroll
        for (int ks = 0; ks < 2; ks++) {
            uint32_t bhf[8], blf[8];
#pragma unroll
            for (int p = 0; p < 2; p++) {
                const uint32_t boff = SWZ(wn * 32 + p * 16 + b_nl, ks * 2 + b_c0);
                LDM4(bhf[p * 4 + 0], bhf[p * 4 + 1], bhf[p * 4 + 2], bhf[p * 4 + 3], bhb + boff);
                LDM4(blf[p * 4 + 0], blf[p * 4 + 1], blf[p * 4 + 2], blf[p * 4 + 3], blb + boff);
            }
#pragma unroll
            for (int mt = 0; mt < 2; mt++) {
                uint32_t ahf[4], alf[4];
                const uint32_t aoff = SWZ(wm * 32 + mt * 16 + a_ml, ks * 2 + a_c0);
                LDM4(ahf[0], ahf[1], ahf[2], ahf[3], ahb + aoff);
                LDM4(alf[0], alf[1], alf[2], alf[3], alb + aoff);
#pragma unroll
                for (int nt = 0; nt < 4; nt++) {
                    const int bi = (nt >> 1) * 4 + (nt & 1) * 2;
                    float* c = acc[mt][nt];
                    MMA16B(c, ahf, bhf[bi], bhf[bi + 1]);
                    MMA16B(c, ahf, blf[bi], blf[bi + 1]);
                    MMA16B(c, alf, bhf[bi], bhf[bi + 1]);
                }
            }
        }
    };

    issue(0);
    for (int s2 = 0; s2 < S2; s2++) {
        CPWAIT0();
        __syncthreads();
        if (s2 + 1 < S2) issue(s2 + 1);
        const uint32_t stb = sb + (uint32_t)(s2 & 1) * STG64;
        compute32(stb);
        compute32(stb + STG32);
        __syncthreads();
    }

    const int er = lane >> 2, ec = (lane & 3) * 2;
#pragma unroll
    for (int mt = 0; mt < 2; mt++) {
        const int m = m0 + wm * 32 + mt * 16 + er;
#pragma unroll
        for (int nt = 0; nt < 4; nt++) {
            const int n = n0 + wn * 32 + nt * 8 + ec;
            float bn0 = 0.f, bn1 = 0.f;
            if (BIAS == 1) { bn0 = bias[n]; bn1 = bias[n + 1]; }
            const float* c = acc[mt][nt];
            float v00 = c[0] + bn0, v01 = c[1] + bn1;
            float v10 = c[2] + bn0, v11 = c[3] + bn1;
            if (OUT == 0) {
                *reinterpret_cast<float2*>(Cf + (long)m * ldc + n) = make_float2(v00, v01);
                *reinterpret_cast<float2*>(Cf + (long)(m + 8) * ldc + n) = make_float2(v10, v11);
            } else {
                bf16 h0, l0, h1, l1;
                bsplit(v00, h0, l0); bsplit(v01, h1, l1);
                *reinterpret_cast<__nv_bfloat162*>(Ch + (long)m * ldc + n) = __halves2bfloat162(h0, h1);
                *reinterpret_cast<__nv_bfloat162*>(Cl + (long)m * ldc + n) = __halves2bfloat162(l0, l1);
                bsplit(v10, h0, l0); bsplit(v11, h1, l1);
                *reinterpret_cast<__nv_bfloat162*>(Ch + (long)(m + 8) * ldc + n) = __halves2bfloat162(h0, h1);
                *reinterpret_cast<__nv_bfloat162*>(Cl + (long)(m + 8) * ldc + n) = __halves2bfloat162(l0, l1);
            }
        }
    }
}

// ---------------------------------------------------------------------------
// fp16 single-pass core. MT=128: 512 thr. MT=64: 256 thr. BK=64, 3 stages.
// ---------------------------------------------------------------------------
template <int MT, int BIAS, int OUT>
__device__ __forceinline__ void gemm_core_h(
    const __half* __restrict__ A, int lda, const __half* __restrict__ B, int ldb,
    const float* __restrict__ bias,
    float* __restrict__ Cf, __half* __restrict__ Chf, int ldc,
    int m0, int n0, int Keff)
{
    constexpr int ABY = MT * 64;
    constexpr int BBY = 8192;
    constexpr int STG32 = ABY + BBY;
    constexpr int STG64 = 2 * STG32;
    extern __shared__ uint16_t sm[];
    const uint32_t sb = smem_u32(sm);
    const int tid = threadIdx.x, lane = tid & 31, wrp = tid >> 5;
    const int wm = wrp >> 2, wn = wrp & 3;
    const int S2 = Keff >> 6;

    const int a_ml = (lane & 7) + ((lane >> 3) & 1) * 8;
    const int a_c0 = lane >> 4;
    const int b_nl = (lane & 7) + ((lane >> 4) << 3);
    const int b_c0 = (lane >> 3) & 1;

    const int row = tid >> 2, ch = tid & 3;
    const __half* Ap = A + (long)(m0 + row) * lda + ch * 8;
    const __half* Bp = B + (long)(n0 + row) * ldb + ch * 8;
    const uint32_t swz = SWZ(row, ch);
    const uint32_t swz2 = SWZ(row + 64, ch);

    auto issue32 = [&](int k32, uint32_t db) {
        const int k0 = k32 << 5;
        CPA16(db + swz, Ap + k0);
        CPA16(db + ABY + swz, Bp + k0);
        if (MT == 64)
            CPA16(db + ABY + swz2, Bp + (long)64 * ldb + k0);
    };
    auto issue = [&](int s2) {
        const uint32_t db = sb + (uint32_t)(s2 % 3) * STG64;
        issue32(2 * s2, db);
        issue32(2 * s2 + 1, db + STG32);
        CPCOMMIT();
    };

    float acc[2][4][4] = {};

    auto compute32 = [&](uint32_t stb) {
#pragma unroll
        for (int ks = 0; ks < 2; ks++) {
            uint32_t bhf[8];
#pragma unroll
            for (int p = 0; p < 2; p++) {
                const uint32_t boff = SWZ(wn * 32 + p * 16 + b_nl, ks * 2 + b_c0);
                LDM4(bhf[p * 4 + 0], bhf[p * 4 + 1], bhf[p * 4 + 2], bhf[p * 4 + 3], stb + ABY + boff);
            }
#pragma unroll
            for (int mt = 0; mt < 2; mt++) {
                uint32_t ahf[4];
                const uint32_t aoff = SWZ(wm * 32 + mt * 16 + a_ml, ks * 2 + a_c0);
                LDM4(ahf[0], ahf[1], ahf[2], ahf[3], stb + aoff);
#pragma unroll
                for (int nt = 0; nt < 4; nt++) {
                    const int bi = (nt >> 1) * 4 + (nt & 1) * 2;
                    MMA16H(acc[mt][nt], ahf, bhf[bi], bhf[bi + 1]);
                }
            }
        }
    };

    issue(0); issue(1);
    for (int s2 = 0; s2 < S2; s2++) {
        CPWAIT1();
        __syncthreads();
        if (s2 + 2 < S2) issue(s2 + 2); else CPCOMMIT();
        const uint32_t stb = sb + (uint32_t)(s2 % 3) * STG64;
        compute32(stb);
        compute32(stb + STG32);
    }

    const int er = lane >> 2, ec = (lane & 3) * 2;
#pragma unroll
    for (int mt = 0; mt < 2; mt++) {
        const int m = m0 + wm * 32 + mt * 16 + er;
        float bm0 = 0.f, bm8 = 0.f;
        if (BIAS == 2) { bm0 = bias[m]; bm8 = bias[m + 8]; }
#pragma unroll
        for (int nt = 0; nt < 4; nt++) {
            const int n = n0 + wn * 32 + nt * 8 + ec;
            float bn0 = 0.f, bn1 = 0.f;
            if (BIAS == 1) { bn0 = bias[n]; bn1 = bias[n + 1]; }
            const float* c = acc[mt][nt];
            float v00 = c[0] + bn0 + bm0, v01 = c[1] + bn1 + bm0;
            float v10 = c[2] + bn0 + bm8, v11 = c[3] + bn1 + bm8;
            if (OUT == 0) {
                *reinterpret_cast<float2*>(Cf + (long)m * ldc + n) = make_float2(v00, v01);
                *reinterpret_cast<float2*>(Cf + (long)(m + 8) * ldc + n) = make_float2(v10, v11);
            } else {
                *reinterpret_cast<__half2*>(Chf + (long)m * ldc + n) = __floats2half2_rn(v00, v01);
                *reinterpret_cast<__half2*>(Chf + (long)(m + 8) * ldc + n) = __floats2half2_rn(v10, v11);
            }
        }
    }
}

// ---------------------------------------------------------------------------
struct QKVP {
    const bf16 *xh, *xl;
    const __half *xf;
    const bf16 *qwh, *qwl, *kwh, *kwl;
    const __half *vwf;
    const float *qb, *kb, *vb;
    bf16 *qh, *ql, *kh, *kl;
    __half *vf;
};

__global__ void __launch_bounds__(256, 2) qkv_kernel(QKVP p)
{
    const int bx = blockIdx.x, by = blockIdx.y, bz = blockIdx.z;
    if (bz == 0) {
        gemm_core<1, 1>(p.xh, p.xl, DD, p.qwh, p.qwl, DD, p.qb,
                        nullptr, p.qh, p.ql, DD, by * 64, bx * 128, DD);
    } else if (bz == 1) {
        gemm_core<1, 1>(p.xh, p.xl, DD, p.kwh, p.kwl, DD, p.kb,
                        nullptr, p.kh, p.kl, DD, by * 64, bx * 128, DD);
    } else {
        const int b = by >> 4, dt = by & 15;
        gemm_core_h<64, 2, 1>(p.vwf, DD, p.xf + (long)b * MD, DD, p.vb,
                              nullptr, p.vf + (long)b * MD, TT, dt * 64, bx * 128, DD);
    }
}

__global__ void __launch_bounds__(256, 2) sc_kernel(const bf16* __restrict__ qh, const bf16* __restrict__ ql,
                                                    const bf16* __restrict__ kh, const bf16* __restrict__ kl,
                                                    float* __restrict__ a)
{
    const int bx = blockIdx.x, by = blockIdx.y, b = blockIdx.z;
    if (2 * bx > by) return;
    gemm_core<0, 0>(qh + (long)b * MD, ql + (long)b * MD, DD,
                    kh + (long)b * MD, kl + (long)b * MD, DD, nullptr,
                    a + (long)b * AA, nullptr, nullptr, TT, by * 64, bx * 128, DD);
}

__global__ void __launch_bounds__(512, 2) av_kernel(const __half* __restrict__ wf,
                                                    const __half* __restrict__ vf,
                                                    float* __restrict__ o)
{
    const int bx = blockIdx.x, by = blockIdx.y, b = blockIdx.z;
    gemm_core_h<128, 0, 0>(wf + (long)b * AA, TT, vf + (long)b * MD, TT, nullptr,
                           o + (long)b * MD, nullptr, DD,
                           by * 128, bx * 128, min(TT, by * 128 + 128));
}

__global__ void __launch_bounds__(512, 2) vocab_kernel(const __half* __restrict__ xn,
                                                       const __half* __restrict__ dwf,
                                                       const float* __restrict__ db,
                                                       float* __restrict__ out)
{
    gemm_core_h<128, 1, 0>(xn, DD, dwf, DD, db, out, nullptr, VV,
                           blockIdx.x * 128, blockIdx.y * 128, DD);
}

// ---------------------------------------------------------------------------
__global__ void splitw_kernel(const float4* __restrict__ src, bf16* __restrict__ h,
                              bf16* __restrict__ l, int n4)
{
    int i = blockIdx.x * blockDim.x + threadIdx.x;
    if (i >= n4) return;
    float4 v = src[i];
    bf16 h0, l0, h1, l1, h2, l2, h3, l3;
    bsplit(v.x, h0, l0); bsplit(v.y, h1, l1); bsplit(v.z, h2, l2); bsplit(v.w, h3, l3);
    *reinterpret_cast<__nv_bfloat162*>(h + (long)i * 4)     = __halves2bfloat162(h0, h1);
    *reinterpret_cast<__nv_bfloat162*>(h + (long)i * 4 + 2) = __halves2bfloat162(h2, h3);
    *reinterpret_cast<__nv_bfloat162*>(l + (long)i * 4)     = __halves2bfloat162(l0, l1);
    *reinterpret_cast<__nv_bfloat162*>(l + (long)i * 4 + 2) = __halves2bfloat162(l2, l3);
}

__global__ void tohalf_kernel(const float4* __restrict__ src, __half* __restrict__ dst, int n4)
{
    int i = blockIdx.x * blockDim.x + threadIdx.x;
    if (i >= n4) return;
    float4 v = src[i];
    *reinterpret_cast<__half2*>(dst + (long)i * 4)     = __floats2half2_rn(v.x, v.y);
    *reinterpret_cast<__half2*>(dst + (long)i * 4 + 2) = __floats2half2_rn(v.z, v.w);
}

__device__ __forceinline__ void store_x3(float4 v, long off, float* X,
                                         bf16* xh, bf16* xl, __half* xf)
{
    if (X) *reinterpret_cast<float4*>(X + off) = v;
    bf16 h0, l0, h1, l1, h2, l2, h3, l3;
    bsplit(v.x, h0, l0); bsplit(v.y, h1, l1); bsplit(v.z, h2, l2); bsplit(v.w, h3, l3);
    *reinterpret_cast<__nv_bfloat162*>(xh + off)     = __halves2bfloat162(h0, h1);
    *reinterpret_cast<__nv_bfloat162*>(xh + off + 2) = __halves2bfloat162(h2, h3);
    *reinterpret_cast<__nv_bfloat162*>(xl + off)     = __halves2bfloat162(l0, l1);
    *reinterpret_cast<__nv_bfloat162*>(xl + off + 2) = __halves2bfloat162(l2, l3);
    *reinterpret_cast<__half2*>(xf + off)     = __floats2half2_rn(v.x, v.y);
    *reinterpret_cast<__half2*>(xf + off + 2) = __floats2half2_rn(v.z, v.w);
}

__global__ void embed_pe_kernel(const int* __restrict__ src, const float* __restrict__ pe,
                                const float* __restrict__ embed, float* __restrict__ x,
                                bf16* __restrict__ xh, bf16* __restrict__ xl, __half* __restrict__ xf)
{
    int row = blockIdx.x, b = row >> 10;
    long tok = src[row];
    const float4* e = reinterpret_cast<const float4*>(embed + tok * (long)DD);
    const float4* p = reinterpret_cast<const float4*>(pe + (long)b * DD);
    int i = threadIdx.x;
    float4 ev = e[i], pv = p[i];
    float4 v = make_float4(ev.x + pv.x, ev.y + pv.y, ev.z + pv.z, ev.w + pv.w);
    store_x3(v, (long)row * DD + i * 4, x, xh, xl, xf);
}

__global__ void softmax_kernel(const float* __restrict__ A, __half* __restrict__ Wf)
{
    int t = blockIdx.x, b = blockIdx.y;
    const float* row = A + ((long)b * TT + t) * TT;
    __half* wf = Wf + ((long)b * TT + t) * TT;
    int n = t + 1, i = threadIdx.x;
    __shared__ float red[256];
    __shared__ float rowe[TT];
    float m = -1e30f;
    for (int s = i; s < n; s += 256) m = fmaxf(m, row[s]);
    red[i] = m; __syncthreads();
    for (int st = 128; st > 0; st >>= 1) { if (i < st) red[i] = fmaxf(red[i], red[i + st]); __syncthreads(); }
    m = red[0]; __syncthreads();
    float sum = 0.f;
    for (int s = i; s < n; s += 256) { float e = expf(row[s] - m); rowe[s] = e; sum += e; }
    red[i] = sum; __syncthreads();
    for (int st = 128; st > 0; st >>= 1) { if (i < st) red[i] += red[i + st]; __syncthreads(); }
    float inv = 1.0f / red[0];
    for (int s = i; s < TT; s += 256)
        wf[s] = (s < n) ? __float2half_rn(rowe[s] * inv) : __float2half_rn(0.f);
}

__global__ void ln_res_kernel(const float* __restrict__ O, const float* __restrict__ w,
                              const float* __restrict__ bb, float* __restrict__ X,
                              bf16* __restrict__ xh, bf16* __restrict__ xl, __half* __restrict__ xf)
{
    int row = blockIdx.x, i = threadIdx.x;
    const float4 o = reinterpret_cast<const float4*>(O + (long)row * DD)[i];
    float4* x4 = reinterpret_cast<float4*>(X + (long)row * DD);
    __shared__ float red[256];
    red[i] = o.x + o.y + o.z + o.w; __syncthreads();
    for (int st = 128; st > 0; st >>= 1) { if (i < st) red[i] += red[i + st]; __syncthreads(); }
    float mu = red[0] * (1.0f / DD); __syncthreads();
    float dx = o.x - mu, dy = o.y - mu, dz = o.z - mu, dw_ = o.w - mu;
    red[i] = dx * dx + dy * dy + dz * dz + dw_ * dw_; __syncthreads();
    for (int st = 128; st > 0; st >>= 1) { if (i < st) red[i] += red[i + st]; __syncthreads(); }
    float rstd = rsqrtf(red[0] * (1.0f / DD) + 1e-6f);
    float4 wv = reinterpret_cast<const float4*>(w)[i];
    float4 bv = reinterpret_cast<const float4*>(bb)[i];
    float4 xv = x4[i];
    xv.x += dx * rstd * wv.x + bv.x;
    xv.y += dy * rstd * wv.y + bv.y;
    xv.z += dz * rstd * wv.z + bv.z;
    xv.w += dw_ * rstd * wv.w + bv.w;
    x4[i] = xv;
    store_x3(xv, (long)row * DD + i * 4, nullptr, xh, xl, xf);
}

__global__ void final_ln_kernel(const float* __restrict__ X, const float* __restrict__ fw,
                                const float* __restrict__ fb, __half* __restrict__ Y)
{
    int row = blockIdx.x, i = threadIdx.x;
    const float4 x = reinterpret_cast<const float4*>(X + (long)row * DD)[i];
    __shared__ float red[256];
    red[i] = x.x + x.y + x.z + x.w; __syncthreads();
    for (int st = 128; st > 0; st >>= 1) { if (i < st) red[i] += red[i + st]; __syncthreads(); }
    float mu = red[0] * (1.0f / DD); __syncthreads();
    float dx = x.x - mu, dy = x.y - mu, dz = x.z - mu, dw_ = x.w - mu;
    red[i] = dx * dx + dy * dy + dz * dz + dw_ * dw_; __syncthreads();
    for (int st = 128; st > 0; st >>= 1) { if (i < st) red[i] += red[i + st]; __syncthreads(); }
    float rstd = rsqrtf(red[0] * (1.0f / DD) + 1e-5f);
    float4 wv = reinterpret_cast<const float4*>(fw)[i];
    float4 bv = reinterpret_cast<const float4*>(fb)[i];
    long off = (long)row * DD + i * 4;
    *reinterpret_cast<__half2*>(Y + off)     = __floats2half2_rn(dx * rstd * wv.x + bv.x, dy * rstd * wv.y + bv.y);
    *reinterpret_cast<__half2*>(Y + off + 2) = __floats2half2_rn(dz * rstd * wv.z + bv.z, dw_ * rstd * wv.w + bv.w);
}

// ---------------------------------------------------------------------------
extern "C" void kernel_launch(void* const* d_in, const int* in_sizes, int n_in,
                              void* d_out, int out_size)
{
    const int*   src = (const int*)d_in[0];
    const float* pe  = (const float*)d_in[1];
    const float* emb = (const float*)d_in[2];
    const float* qw  = (const float*)d_in[3];
    const float* qb  = (const float*)d_in[4];
    const float* kw  = (const float*)d_in[5];
    const float* kb  = (const float*)d_in[6];
    const float* vw  = (const float*)d_in[7];
    const float* vb  = (const float*)d_in[8];
    const float* lnw = (const float*)d_in[9];
    const float* lnb = (const float*)d_in[10];
    const float* fw  = (const float*)d_in[11];
    const float* fb  = (const float*)d_in[12];
    const float* dw  = (const float*)d_in[13];
    const float* db  = (const float*)d_in[14];
    float* out = (float*)d_out;

#define GA(sym, var) void* var##_; cudaGetSymbolAddress(&var##_, sym)
    GA(g_x, x);  GA(g_a, a);  GA(g_o, o);
    GA(g_xh, xh); GA(g_xl, xl); GA(g_xf, xf);
    GA(g_qh, qh); GA(g_ql, ql); GA(g_kh, kh); GA(g_kl, kl);
    GA(g_vf, vf); GA(g_wf, wf);
    GA(g_qwh, qwh); GA(g_qwl, qwl); GA(g_kwh, kwh); GA(g_kwl, kwl);
    GA(g_vwf, vwf); GA(g_dwf, dwf); GA(g_xnf, xnf);
#undef GA

    const int SMQ = 2 * 49152;                   // 98304 (split MT=64 double buffer)
    const int SMH = 3 * 2 * (128 * 64 + 8192);   // 98304 (fp16 MT=128, 3 stages)
    cudaFuncSetAttribute(qkv_kernel,   cudaFuncAttributeMaxDynamicSharedMemorySize, SMQ);
    cudaFuncSetAttribute(sc_kernel,    cudaFuncAttributeMaxDynamicSharedMemorySize, SMQ);
    cudaFuncSetAttribute(av_kernel,    cudaFuncAttributeMaxDynamicSharedMemorySize, SMH);
    cudaFuncSetAttribute(vocab_kernel, cudaFuncAttributeMaxDynamicSharedMemorySize, SMH);

    {
        const int n4w = LL * DD * DD / 4;
        splitw_kernel<<<(n4w + 511) / 512, 512>>>((const float4*)qw, (bf16*)qwh_, (bf16*)qwl_, n4w);
        splitw_kernel<<<(n4w + 511) / 512, 512>>>((const float4*)kw, (bf16*)kwh_, (bf16*)kwl_, n4w);
        tohalf_kernel<<<(n4w + 511) / 512, 512>>>((const float4*)vw, (__half*)vwf_, n4w);
        const int n4d = VV * DD / 4;
        tohalf_kernel<<<(n4d + 511) / 512, 512>>>((const float4*)dw, (__half*)dwf_, n4d);
    }

    embed_pe_kernel<<<BB * TT, 256>>>(src, pe, emb, (float*)x_, (bf16*)xh_, (bf16*)xl_, (__half*)xf_);

    dim3 gqkv(DD / 128, (BB * TT) / 64, 3);   // 8 x 32 x 3
    dim3 gsc(TT / 128, TT / 64, BB);
    dim3 gav(TT / 128, TT / 128, BB);
    for (int l = 0; l < LL; l++) {
        const long wo = (long)l * DD * DD;
        QKVP p;
        p.xh = (const bf16*)xh_; p.xl = (const bf16*)xl_; p.xf = (const __half*)xf_;
        p.qwh = (const bf16*)qwh_ + wo; p.qwl = (const bf16*)qwl_ + wo;
        p.kwh = (const bf16*)kwh_ + wo; p.kwl = (const bf16*)kwl_ + wo;
        p.vwf = (const __half*)vwf_ + wo;
        p.qb = qb + l * DD; p.kb = kb + l * DD; p.vb = vb + l * DD;
        p.qh = (bf16*)qh_; p.ql = (bf16*)ql_;
        p.kh = (bf16*)kh_; p.kl = (bf16*)kl_;
        p.vf = (__half*)vf_;
        qkv_kernel<<<gqkv, 256, SMQ>>>(p);
        sc_kernel<<<gsc, 256, SMQ>>>((const bf16*)qh_, (const bf16*)ql_,
                                     (const bf16*)kh_, (const bf16*)kl_, (float*)a_);
        softmax_kernel<<<dim3(TT, BB), 256>>>((const float*)a_, (__half*)wf_);
        av_kernel<<<gav, 512, SMH>>>((const __half*)wf_, (const __half*)vf_, (float*)o_);
        ln_res_kernel<<<BB * TT, 256>>>((const float*)o_, lnw + l * DD, lnb + l * DD,
                                        (float*)x_, (bf16*)xh_, (bf16*)xl_, (__half*)xf_);
    }

    final_ln_kernel<<<BB * TT, 256>>>((const float*)x_, fw, fb, (__half*)xnf_);
    dim3 gf((BB * TT) / 128, VV / 128);
    vocab_kernel<<<gf, 512, SMH>>>((const __half*)xnf_, (const __half*)dwf_, db, out);
}